// round 1
// baseline (speedup 1.0000x reference)
#include <cuda_runtime.h>

// Problem constants (fixed shapes from reference):
// ypred: [B=8, L=32, J=128, N=512] fp32   -> d_in[0], 16,777,216 elems
// xyz:   [B=8, L=32, N=512, 3]     fp32   -> d_in[1],    393,216 elems
// out:   scalar fp32 mean
#define NPTS 512
#define JDIM 128
#define JCHUNK 32
#define NBL 256

__device__ double g_partials[NBL];

__global__ __launch_bounds__(512, 2)
void cll_fused_kernel(const float* __restrict__ ypred,
                      const float* __restrict__ xyz) {
    __shared__ float4 pt[NPTS];                 // (x, y, z, |x|^2) per point
    __shared__ float  tile[JCHUNK][NPTS];       // ypred chunk [j][n]
    __shared__ double red[512];

    const int bl  = blockIdx.x;
    const int tid = threadIdx.x;

    // ---- load xyz points, compute squared norms (fixed FMA order!) ----
    {
        const float* xb = xyz + (size_t)bl * NPTS * 3;
        float x = xb[tid * 3 + 0];
        float y = xb[tid * 3 + 1];
        float z = xb[tid * 3 + 2];
        // sq = z*z + (y*y + (x*x))  -- same assoc order as dot below so that
        // dot(n,n) == sq[n] bit-exactly => diagonal d2 is exactly 0.0f.
        float sq = fmaf(z, z, fmaf(y, y, x * x));
        pt[tid] = make_float4(x, y, z, sq);
    }
    __syncthreads();

    // ---- phase 1: per-row argmax / masked argmin of d2 (mm-trick) ----
    int imax = 0, imin = 0;
    {
        const float4 me = pt[tid];
        const float xn = me.x, yn = me.y, zn = me.z, sqn = me.w;
        float bmax = -3.0e38f;
        float bmin =  3.0e38f;
        #pragma unroll 8
        for (int m = 0; m < NPTS; ++m) {
            float4 p = pt[m];
            // identical FMA ordering as sq computation
            float dot = fmaf(zn, p.z, fmaf(yn, p.y, xn * p.x));
            float s   = sqn + p.w;
            float val = fmaf(dot, -2.0f, s);   // d2 = sq[n]+sq[m]-2*dot
            // argmax over dist (monotone in d2); strict > => first occurrence
            if (val > bmax) { bmax = val; imax = m; }
            // masked argmin: dist==0 (d2<=0) masked; diag hits val==0 exactly
            if (val > 0.0f && val < bmin) { bmin = val; imin = m; }
        }
    }

    // ---- phase 2: two gathered J=128 dot products per row ----
    const float* yb = ypred + (size_t)bl * JDIM * NPTS;
    float accmax = 0.0f, accmin = 0.0f;

    #pragma unroll 1
    for (int c = 0; c < JDIM / JCHUNK; ++c) {
        __syncthreads();
        // coalesced float4 copy: tile row-major [j][n] matches gmem layout
        const float4* src = (const float4*)(yb + (size_t)c * JCHUNK * NPTS);
        float4* dst = (float4*)&tile[0][0];
        #pragma unroll
        for (int k = 0; k < (JCHUNK * NPTS / 4) / 512; ++k) {
            dst[tid + k * 512] = src[tid + k * 512];
        }
        __syncthreads();

        #pragma unroll
        for (int j = 0; j < JCHUNK; ++j) {
            float a = tile[j][tid];
            accmax = fmaf(a, tile[j][imax], accmax);
            accmin = fmaf(a, tile[j][imin], accmin);
        }
    }

    // ---- deterministic block tree-reduction of (sim_max - sim_min) ----
    red[tid] = (double)(accmax - accmin);
    __syncthreads();
    #pragma unroll
    for (int s = 256; s > 0; s >>= 1) {
        if (tid < s) red[tid] += red[tid + s];
        __syncthreads();
    }
    if (tid == 0) g_partials[bl] = red[0];
}

__global__ void cll_finalize_kernel(float* __restrict__ out) {
    __shared__ double red[NBL];
    const int tid = threadIdx.x;
    red[tid] = g_partials[tid];
    __syncthreads();
    #pragma unroll
    for (int s = NBL / 2; s > 0; s >>= 1) {
        if (tid < s) red[tid] += red[tid + s];
        __syncthreads();
    }
    if (tid == 0) {
        out[0] = (float)(red[0] / (double)(NBL * NPTS));
    }
}

extern "C" void kernel_launch(void* const* d_in, const int* in_sizes, int n_in,
                              void* d_out, int out_size) {
    const float* ypred = (const float*)d_in[0];
    const float* xyz   = (const float*)d_in[1];
    float* out = (float*)d_out;

    cll_fused_kernel<<<NBL, 512>>>(ypred, xyz);
    cll_finalize_kernel<<<1, NBL>>>(out);
}

// round 2
// speedup vs baseline: 1.0684x; 1.0684x over previous
#include <cuda_runtime.h>

// ypred: [B=8, L=32, J=128, N=512] fp32 -> d_in[0]
// xyz:   [B=8, L=32, N=512, 3]     fp32 -> d_in[1]
// out:   scalar fp32 mean
#define NPTS 512
#define JDIM 128
#define JCHUNK 32
#define NBL 256

__device__ double g_partials[NBL];
__device__ unsigned int g_ticket = 0;

// ---- packed f32x2 helpers (sm_100+) ----
__device__ __forceinline__ unsigned long long pack2(float lo, float hi) {
    unsigned long long r;
    asm("mov.b64 %0, {%1, %2};" : "=l"(r) : "f"(lo), "f"(hi));
    return r;
}
__device__ __forceinline__ void unpack2(unsigned long long v, float& lo, float& hi) {
    asm("mov.b64 {%0, %1}, %2;" : "=f"(lo), "=f"(hi) : "l"(v));
}
__device__ __forceinline__ unsigned long long mul2(unsigned long long a, unsigned long long b) {
    unsigned long long d;
    asm("mul.rn.f32x2 %0, %1, %2;" : "=l"(d) : "l"(a), "l"(b));
    return d;
}
__device__ __forceinline__ unsigned long long fma2(unsigned long long a, unsigned long long b,
                                                   unsigned long long c) {
    unsigned long long d;
    asm("fma.rn.f32x2 %0, %1, %2, %3;" : "=l"(d) : "l"(a), "l"(b), "l"(c));
    return d;
}

__global__ __launch_bounds__(512, 2)
void cll_fused_kernel(const float* __restrict__ ypred,
                      const float* __restrict__ xyz,
                      float* __restrict__ out) {
    // packed point tables: pA[m2]=(x0,x1,y0,y1), pB[m2]=(z0,z1,sq0,sq1)
    __shared__ float4 pA[NPTS / 2];
    __shared__ float4 pB[NPTS / 2];
    __shared__ float  tile[JCHUNK][NPTS];
    __shared__ double red[512];
    __shared__ int    amLast;

    const int bl  = blockIdx.x;
    const int tid = threadIdx.x;

    // ---- load xyz, compute squared norm with FIXED fma order ----
    float xn, yn, zn, sqn;
    {
        const float* xb = xyz + (size_t)bl * NPTS * 3;
        xn = xb[tid * 3 + 0];
        yn = xb[tid * 3 + 1];
        zn = xb[tid * 3 + 2];
        // same assoc order as packed dot below => dot(n,n) == sqn bit-exact
        sqn = fmaf(zn, zn, fmaf(yn, yn, xn * xn));
        float* fA = (float*)pA;
        float* fB = (float*)pB;
        int base = (tid >> 1) * 4 + (tid & 1);
        fA[base + 0] = xn;
        fA[base + 2] = yn;
        fB[base + 0] = zn;
        fB[base + 2] = sqn;
    }
    __syncthreads();

    // ---- phase 1: argmax / masked argmin of val' = sq_m - 2*dot(n,m) ----
    // (shifted by -sq_n vs true d2; ordering identical, diagonal is exactly
    //  -sq_n because fma(s,-2,s) == -s, so mask v > -sq_n excludes it exactly)
    int imax = 0, imin = 0;
    {
        const unsigned long long x2 = pack2(xn, xn);
        const unsigned long long y2 = pack2(yn, yn);
        const unsigned long long z2 = pack2(zn, zn);
        const unsigned long long c2 = pack2(-2.0f, -2.0f);
        const float negsq = -sqn;
        float bmax = -3.0e38f;
        float bmin =  3.0e38f;
        const ulonglong2* A = (const ulonglong2*)pA;
        const ulonglong2* B = (const ulonglong2*)pB;
        #pragma unroll 4
        for (int m2 = 0; m2 < NPTS / 2; ++m2) {
            ulonglong2 a = A[m2];   // (x0,x1) (y0,y1)
            ulonglong2 b = B[m2];   // (z0,z1) (sq0,sq1)
            unsigned long long dot = mul2(x2, a.x);
            dot = fma2(y2, a.y, dot);
            dot = fma2(z2, b.x, dot);
            unsigned long long val = fma2(dot, c2, b.y);
            float v0, v1;
            unpack2(val, v0, v1);

            // pairwise tournament for argmax (first occurrence on ties)
            float vm = fmaxf(v0, v1);
            int   mm = (v1 > v0) ? (2 * m2 + 1) : (2 * m2);
            bool  pu = vm > bmax;
            imax = pu ? mm : imax;
            bmax = pu ? vm : bmax;

            // masked argmin, sequential (first occurrence on ties)
            bool q0 = (v0 > negsq) && (v0 < bmin);
            imin = q0 ? (2 * m2) : imin;
            bmin = q0 ? v0 : bmin;
            bool q1 = (v1 > negsq) && (v1 < bmin);
            imin = q1 ? (2 * m2 + 1) : imin;
            bmin = q1 ? v1 : bmin;
        }
    }

    // ---- phase 2: two gathered J=128 dot products per row ----
    const float* yb = ypred + (size_t)bl * JDIM * NPTS;
    float accmax = 0.0f, accmin = 0.0f;

    #pragma unroll 1
    for (int c = 0; c < JDIM / JCHUNK; ++c) {
        __syncthreads();
        const float4* src = (const float4*)(yb + (size_t)c * JCHUNK * NPTS);
        float4* dst = (float4*)&tile[0][0];
        #pragma unroll
        for (int k = 0; k < (JCHUNK * NPTS / 4) / 512; ++k) {
            dst[tid + k * 512] = src[tid + k * 512];
        }
        __syncthreads();

        #pragma unroll
        for (int j = 0; j < JCHUNK; ++j) {
            float a = tile[j][tid];
            accmax = fmaf(a, tile[j][imax], accmax);
            accmin = fmaf(a, tile[j][imin], accmin);
        }
    }

    // ---- deterministic block tree-reduction ----
    red[tid] = (double)(accmax - accmin);
    __syncthreads();
    #pragma unroll
    for (int s = 256; s > 0; s >>= 1) {
        if (tid < s) red[tid] += red[tid + s];
        __syncthreads();
    }

    // ---- fused finalize: last block sums all partials (fixed order) ----
    if (tid == 0) {
        g_partials[bl] = red[0];
        __threadfence();
        unsigned t = atomicAdd(&g_ticket, 1u);
        amLast = (t == NBL - 1) ? 1 : 0;
    }
    __syncthreads();

    if (amLast) {
        const volatile double* gp = (const volatile double*)g_partials;
        red[tid] = (tid < NBL) ? gp[tid] : 0.0;
        __syncthreads();
        #pragma unroll
        for (int s = 256; s > 0; s >>= 1) {
            if (tid < s) red[tid] += red[tid + s];
            __syncthreads();
        }
        if (tid == 0) {
            out[0] = (float)(red[0] / (double)((size_t)NBL * NPTS));
            g_ticket = 0;   // reset for next graph replay
        }
    }
}

extern "C" void kernel_launch(void* const* d_in, const int* in_sizes, int n_in,
                              void* d_out, int out_size) {
    const float* ypred = (const float*)d_in[0];
    const float* xyz   = (const float*)d_in[1];
    float* out = (float*)d_out;
    cll_fused_kernel<<<NBL, 512>>>(ypred, xyz, out);
}

// round 3
// speedup vs baseline: 1.0689x; 1.0005x over previous
#include <cuda_runtime.h>

// ypred: [B=8, L=32, J=128, N=512] fp32 -> d_in[0]
// xyz:   [B=8, L=32, N=512, 3]     fp32 -> d_in[1]
// out:   scalar fp32 mean
#define NPTS 512
#define JDIM 128
#define JCHUNK 32
#define NCHUNK (JDIM / JCHUNK)
#define TSTRIDE 513          // odd stride => warp column reads are conflict-free
#define NBL 256

__device__ double g_partials[NBL];
__device__ unsigned int g_ticket = 0;

// ---- packed f32x2 helpers (sm_100+) ----
__device__ __forceinline__ unsigned long long pack2(float lo, float hi) {
    unsigned long long r;
    asm("mov.b64 %0, {%1, %2};" : "=l"(r) : "f"(lo), "f"(hi));
    return r;
}
__device__ __forceinline__ void unpack2(unsigned long long v, float& lo, float& hi) {
    asm("mov.b64 {%0, %1}, %2;" : "=f"(lo), "=f"(hi) : "l"(v));
}
__device__ __forceinline__ unsigned long long mul2(unsigned long long a, unsigned long long b) {
    unsigned long long d;
    asm("mul.rn.f32x2 %0, %1, %2;" : "=l"(d) : "l"(a), "l"(b));
    return d;
}
__device__ __forceinline__ unsigned long long fma2(unsigned long long a, unsigned long long b,
                                                   unsigned long long c) {
    unsigned long long d;
    asm("fma.rn.f32x2 %0, %1, %2, %3;" : "=l"(d) : "l"(a), "l"(b), "l"(c));
    return d;
}

__global__ __launch_bounds__(512, 2)
void cll_fused_kernel(const float* __restrict__ ypred,
                      const float* __restrict__ xyz,
                      float* __restrict__ out) {
    __shared__ float4 pA[NPTS / 2];              // (x0,x1,y0,y1) per point pair
    __shared__ float4 pB[NPTS / 2];              // (z0,z1,sq0,sq1)
    __shared__ float  tile[JCHUNK * TSTRIDE];    // ypred chunk, stride-513 rows
    __shared__ int    amLast;
    double* red = (double*)pA;                   // alias: pA dead after phase 1

    const int bl  = blockIdx.x;
    const int tid = threadIdx.x;
    const int w   = tid >> 5;
    const int l   = tid & 31;

    const float* yb = ypred + (size_t)bl * (JDIM * NPTS);

    // ---- prefetch ypred chunk 0 under phase 1 (cp.async, 4B, conflict-free) ----
    {
        unsigned db = (unsigned)__cvta_generic_to_shared(tile);
        #pragma unroll
        for (int r = 0; r < JCHUNK; ++r) {
            const float* src = yb + r * NPTS + tid;
            unsigned dst = db + (unsigned)((r * TSTRIDE + tid) * 4);
            asm volatile("cp.async.ca.shared.global [%0], [%1], 4;" :: "r"(dst), "l"(src));
        }
        asm volatile("cp.async.commit_group;" ::: "memory");
    }

    // ---- load xyz, squared norms (fixed fma order => diag d2 exact) ----
    float xn, yn, zn, sqn;
    {
        const float* xb = xyz + (size_t)bl * NPTS * 3;
        xn = xb[tid * 3 + 0];
        yn = xb[tid * 3 + 1];
        zn = xb[tid * 3 + 2];
        sqn = fmaf(zn, zn, fmaf(yn, yn, xn * xn));
        float* fA = (float*)pA;
        float* fB = (float*)pB;
        int base = (tid >> 1) * 4 + (tid & 1);
        fA[base + 0] = xn;
        fA[base + 2] = yn;
        fB[base + 0] = zn;
        fB[base + 2] = sqn;
    }
    __syncthreads();

    // ---- phase 1: argmax / masked argmin, independent even/odd chains ----
    int imax, imin;
    {
        const unsigned long long x2 = pack2(xn, xn);
        const unsigned long long y2 = pack2(yn, yn);
        const unsigned long long z2 = pack2(zn, zn);
        const unsigned long long c2 = pack2(-2.0f, -2.0f);
        const float negsq = -sqn;
        float bmaxA = -3.0e38f, bmaxB = -3.0e38f;
        float bminA =  3.0e38f, bminB =  3.0e38f;
        int imaxA = 0, imaxB = 1, iminA = 0, iminB = 1;
        const ulonglong2* A = (const ulonglong2*)pA;
        const ulonglong2* B = (const ulonglong2*)pB;
        #pragma unroll 8
        for (int m2 = 0; m2 < NPTS / 2; ++m2) {
            ulonglong2 a = A[m2];
            ulonglong2 b = B[m2];
            unsigned long long dot = mul2(x2, a.x);
            dot = fma2(y2, a.y, dot);
            dot = fma2(z2, b.x, dot);
            unsigned long long val = fma2(dot, c2, b.y);  // v = sq_m - 2*dot
            float v0, v1;
            unpack2(val, v0, v1);
            // even stream
            if (v0 > bmaxA) { bmaxA = v0; imaxA = 2 * m2; }
            if (v0 > negsq && v0 < bminA) { bminA = v0; iminA = 2 * m2; }
            // odd stream (independent dependency chain)
            if (v1 > bmaxB) { bmaxB = v1; imaxB = 2 * m2 + 1; }
            if (v1 > negsq && v1 < bminB) { bminB = v1; iminB = 2 * m2 + 1; }
        }
        // merge with exact first-occurrence tie-break
        imax = (bmaxB > bmaxA || (bmaxB == bmaxA && imaxB < imaxA)) ? imaxB : imaxA;
        imin = (bminB < bminA || (bminB == bminA && iminB < iminA)) ? iminB : iminA;
    }

    // ---- phase 2: warp-cooperative conflict-free gathered dots ----
    asm volatile("cp.async.wait_group 0;" ::: "memory");
    __syncthreads();   // chunk 0 ready; also fences pA/pB last readers

    float acc = 0.0f;
    const float* tl = tile + l * TSTRIDE;   // lane l owns j-row l of the chunk
    const float* ta = tl + (w << 5);        // this warp's target columns

    #pragma unroll 1
    for (int c = 0; c < NCHUNK; ++c) {
        #pragma unroll
        for (int i = 0; i < 32; ++i) {
            int mt = __shfl_sync(0xffffffffu, imax, i);  // warp-uniform gather idx
            int nt = __shfl_sync(0xffffffffu, imin, i);
            float a  = ta[i];       // bank (l + w*32+i)%32  : conflict-free
            float b  = tl[mt];      // bank (l + mt)%32      : conflict-free
            float cc = tl[nt];      // bank (l + nt)%32      : conflict-free
            acc = fmaf(a, b - cc, acc);
        }
        if (c + 1 < NCHUNK) {
            __syncthreads();   // everyone done reading chunk c
            unsigned db = (unsigned)__cvta_generic_to_shared(tile);
            const float* ybase = yb + (size_t)(c + 1) * JCHUNK * NPTS;
            #pragma unroll
            for (int r = 0; r < JCHUNK; ++r) {
                const float* src = ybase + r * NPTS + tid;
                unsigned dst = db + (unsigned)((r * TSTRIDE + tid) * 4);
                asm volatile("cp.async.ca.shared.global [%0], [%1], 4;" :: "r"(dst), "l"(src));
            }
            asm volatile("cp.async.commit_group;" ::: "memory");
            asm volatile("cp.async.wait_group 0;" ::: "memory");
            __syncthreads();   // chunk c+1 visible to all
        }
    }

    // ---- deterministic block tree-reduction (red aliases pA) ----
    __syncthreads();
    red[tid] = (double)acc;
    __syncthreads();
    #pragma unroll
    for (int s = 256; s > 0; s >>= 1) {
        if (tid < s) red[tid] += red[tid + s];
        __syncthreads();
    }

    // ---- fused finalize: last block sums partials in fixed order ----
    if (tid == 0) {
        g_partials[bl] = red[0];
        __threadfence();
        unsigned t = atomicAdd(&g_ticket, 1u);
        amLast = (t == NBL - 1) ? 1 : 0;
    }
    __syncthreads();

    if (amLast) {
        const volatile double* gp = (const volatile double*)g_partials;
        red[tid] = (tid < NBL) ? gp[tid] : 0.0;
        __syncthreads();
        #pragma unroll
        for (int s = 256; s > 0; s >>= 1) {
            if (tid < s) red[tid] += red[tid + s];
            __syncthreads();
        }
        if (tid == 0) {
            out[0] = (float)(red[0] / (double)((size_t)NBL * NPTS));
            g_ticket = 0;   // reset for next graph replay
        }
    }
}

extern "C" void kernel_launch(void* const* d_in, const int* in_sizes, int n_in,
                              void* d_out, int out_size) {
    const float* ypred = (const float*)d_in[0];
    const float* xyz   = (const float*)d_in[1];
    float* out = (float*)d_out;
    cll_fused_kernel<<<NBL, 512>>>(ypred, xyz, out);
}

// round 4
// speedup vs baseline: 1.3441x; 1.2574x over previous
#include <cuda_runtime.h>

// ypred: [B=8, L=32, J=128, N=512] fp32 -> d_in[0]
// xyz:   [B=8, L=32, N=512, 3]     fp32 -> d_in[1]
// out:   scalar fp32 mean
#define NPTS 512
#define JDIM 128
#define JCHUNK 32
#define NCHUNK (JDIM / JCHUNK)
#define TSTRIDE 513          // odd stride => warp column reads conflict-free
#define NBL 256

__device__ double g_partials[NBL];
__device__ unsigned int g_ticket = 0;

// ---- packed f32x2 helpers (sm_100+) ----
__device__ __forceinline__ unsigned long long pack2(float lo, float hi) {
    unsigned long long r;
    asm("mov.b64 %0, {%1, %2};" : "=l"(r) : "f"(lo), "f"(hi));
    return r;
}
__device__ __forceinline__ void unpack2(unsigned long long v, float& lo, float& hi) {
    asm("mov.b64 {%0, %1}, %2;" : "=f"(lo), "=f"(hi) : "l"(v));
}
__device__ __forceinline__ unsigned long long mul2(unsigned long long a, unsigned long long b) {
    unsigned long long d;
    asm("mul.rn.f32x2 %0, %1, %2;" : "=l"(d) : "l"(a), "l"(b));
    return d;
}
__device__ __forceinline__ unsigned long long fma2(unsigned long long a, unsigned long long b,
                                                   unsigned long long c) {
    unsigned long long d;
    asm("fma.rn.f32x2 %0, %1, %2, %3;" : "=l"(d) : "l"(a), "l"(b), "l"(c));
    return d;
}

__global__ __launch_bounds__(512, 2)
void cll_fused_kernel(const float* __restrict__ ypred,
                      const float* __restrict__ xyz,
                      float* __restrict__ out) {
    __shared__ float4 pA[NPTS / 2];              // (x0,x1,y0,y1) per point pair
    __shared__ float4 pB[NPTS / 2];              // (z0,z1,sq0,sq1)
    __shared__ float  tile[JCHUNK * TSTRIDE];    // ypred chunk, stride-513 rows
    __shared__ double redbuf[256];
    __shared__ int    amLast;

    const int bl  = blockIdx.x;
    const int tid = threadIdx.x;
    const int w   = tid >> 5;
    const int l   = tid & 31;

    const float* yb = ypred + (size_t)bl * (JDIM * NPTS);
    const float INF = __int_as_float(0x7f800000);

    // ---- prefetch ypred chunk 0 under phase 1 (cp.async 4B, conflict-free) ----
    {
        unsigned db = (unsigned)__cvta_generic_to_shared(tile);
        #pragma unroll
        for (int r = 0; r < JCHUNK; ++r) {
            const float* src = yb + r * NPTS + tid;
            unsigned dst = db + (unsigned)((r * TSTRIDE + tid) * 4);
            asm volatile("cp.async.ca.shared.global [%0], [%1], 4;" :: "r"(dst), "l"(src));
        }
        asm volatile("cp.async.commit_group;" ::: "memory");
    }

    // ---- load xyz, squared norms (fixed fma order => diag v == -sqn exact) ----
    float xn, yn, zn, sqn;
    {
        const float* xb = xyz + (size_t)bl * NPTS * 3;
        xn = xb[tid * 3 + 0];
        yn = xb[tid * 3 + 1];
        zn = xb[tid * 3 + 2];
        sqn = fmaf(zn, zn, fmaf(yn, yn, xn * xn));
        float* fA = (float*)pA;
        float* fB = (float*)pB;
        int base = (tid >> 1) * 4 + (tid & 1);
        fA[base + 0] = xn;
        fA[base + 2] = yn;
        fB[base + 0] = zn;
        fB[base + 2] = sqn;
    }
    __syncthreads();

    // ---- phase 1: pair-tournament argmax / argmin of v = sq_m - 2*dot(n,m) ----
    // Masked-min (reference: d2<=0 masked) only needed where a diagonal can
    // appear: segment s covers pairs [8s,8s+8); warp w's diagonals live in
    // segments {2w, 2w+1} exactly -> warp-uniform branch, no divergence.
    int imax, imin;
    {
        const unsigned long long x2 = pack2(xn, xn);
        const unsigned long long y2 = pack2(yn, yn);
        const unsigned long long z2 = pack2(zn, zn);
        const unsigned long long c2 = pack2(-2.0f, -2.0f);
        const float negsq = -sqn;
        float bmax = -INF, bmin = INF;
        int pmax = 0, pmin = 0;
        const ulonglong2* A = (const ulonglong2*)pA;
        const ulonglong2* B = (const ulonglong2*)pB;

        #pragma unroll 1
        for (int s = 0; s < 32; ++s) {
            const int base = s << 3;
            if ((s >> 1) != w) {
                #pragma unroll
                for (int k = 0; k < 8; ++k) {
                    const int m2 = base + k;
                    ulonglong2 a = A[m2];
                    ulonglong2 b = B[m2];
                    unsigned long long dot = mul2(x2, a.x);
                    dot = fma2(y2, a.y, dot);
                    dot = fma2(z2, b.x, dot);
                    unsigned long long val = fma2(dot, c2, b.y);
                    float v0, v1;
                    unpack2(val, v0, v1);
                    float vm = fmaxf(v0, v1);
                    if (vm > bmax) { bmax = vm; pmax = m2; }
                    float wm = fminf(v0, v1);
                    if (wm < bmin) { bmin = wm; pmin = m2; }
                }
            } else {
                #pragma unroll
                for (int k = 0; k < 8; ++k) {
                    const int m2 = base + k;
                    ulonglong2 a = A[m2];
                    ulonglong2 b = B[m2];
                    unsigned long long dot = mul2(x2, a.x);
                    dot = fma2(y2, a.y, dot);
                    dot = fma2(z2, b.x, dot);
                    unsigned long long val = fma2(dot, c2, b.y);
                    float v0, v1;
                    unpack2(val, v0, v1);
                    float vm = fmaxf(v0, v1);
                    if (vm > bmax) { bmax = vm; pmax = m2; }
                    float w0 = (v0 > negsq) ? v0 : INF;   // mask (diag hits exactly)
                    float w1 = (v1 > negsq) ? v1 : INF;
                    float wm = fminf(w0, w1);
                    if (wm < bmin) { bmin = wm; pmin = m2; }
                }
            }
        }

        // O(1) epilogue: resolve even/odd inside winning pairs with exact
        // first-occurrence semantics (recompute with identical arithmetic).
        {
            ulonglong2 a = A[pmax];
            ulonglong2 b = B[pmax];
            unsigned long long dot = mul2(x2, a.x);
            dot = fma2(y2, a.y, dot);
            dot = fma2(z2, b.x, dot);
            unsigned long long val = fma2(dot, c2, b.y);
            float v0, v1;
            unpack2(val, v0, v1);
            imax = 2 * pmax + ((v0 == bmax) ? 0 : 1);

            a = A[pmin];
            b = B[pmin];
            dot = mul2(x2, a.x);
            dot = fma2(y2, a.y, dot);
            dot = fma2(z2, b.x, dot);
            val = fma2(dot, c2, b.y);
            float u0, u1;
            unpack2(val, u0, u1);
            imin = 2 * pmin + (((u0 > negsq) && (u0 == bmin)) ? 0 : 1);
        }
    }

    // ---- phase 2: warp-cooperative conflict-free gathered dots ----
    asm volatile("cp.async.wait_group 0;" ::: "memory");
    __syncthreads();   // chunk 0 ready; pA/pB readers done

    const int packed = imax | (imin << 16);
    float acc = 0.0f;
    const float* tl = tile + l * TSTRIDE;   // lane l owns j-row l
    const float* ta = tl + (w << 5);        // this warp's target columns

    #pragma unroll 1
    for (int c = 0; c < NCHUNK; ++c) {
        #pragma unroll
        for (int i = 0; i < 32; ++i) {
            int pk = __shfl_sync(0xffffffffu, packed, i);  // warp-uniform idx pair
            int mt = pk & 0xffff;
            int nt = ((unsigned)pk) >> 16;
            float a  = ta[i];       // bank (l + w*32+i)%32 : conflict-free
            float b  = tl[mt];      // bank (l + mt)%32     : conflict-free
            float cc = tl[nt];      // bank (l + nt)%32     : conflict-free
            acc = fmaf(a, b - cc, acc);
        }
        if (c + 1 < NCHUNK) {
            __syncthreads();   // everyone done reading chunk c
            unsigned db = (unsigned)__cvta_generic_to_shared(tile);
            const float* ybase = yb + (size_t)(c + 1) * JCHUNK * NPTS;
            #pragma unroll
            for (int r = 0; r < JCHUNK; ++r) {
                const float* src = ybase + r * NPTS + tid;
                unsigned dst = db + (unsigned)((r * TSTRIDE + tid) * 4);
                asm volatile("cp.async.ca.shared.global [%0], [%1], 4;" :: "r"(dst), "l"(src));
            }
            asm volatile("cp.async.commit_group;" ::: "memory");
            asm volatile("cp.async.wait_group 0;" ::: "memory");
            __syncthreads();   // chunk c+1 visible
        }
    }

    // ---- deterministic reduction: warp butterfly, then fixed-order sum ----
    double d = (double)acc;
    #pragma unroll
    for (int off = 16; off > 0; off >>= 1)
        d += __shfl_xor_sync(0xffffffffu, d, off);
    if (l == 0) redbuf[w] = d;
    __syncthreads();

    if (tid == 0) {
        double s = 0.0;
        #pragma unroll
        for (int i = 0; i < 16; ++i) s += redbuf[i];
        g_partials[bl] = s;
        __threadfence();
        unsigned t = atomicAdd(&g_ticket, 1u);
        amLast = (t == NBL - 1) ? 1 : 0;
    }
    __syncthreads();

    // ---- fused finalize: last block sums partials in fixed order ----
    if (amLast) {
        if (tid < NBL) redbuf[tid] = ((const volatile double*)g_partials)[tid];
        __syncthreads();
        #pragma unroll
        for (int s2 = NBL / 2; s2 > 0; s2 >>= 1) {
            if (tid < s2) redbuf[tid] += redbuf[tid + s2];
            __syncthreads();
        }
        if (tid == 0) {
            out[0] = (float)(redbuf[0] / (double)((size_t)NBL * NPTS));
            g_ticket = 0;   // reset for next graph replay
        }
    }
}

extern "C" void kernel_launch(void* const* d_in, const int* in_sizes, int n_in,
                              void* d_out, int out_size) {
    const float* ypred = (const float*)d_in[0];
    const float* xyz   = (const float*)d_in[1];
    float* out = (float*)d_out;
    cll_fused_kernel<<<NBL, 512>>>(ypred, xyz, out);
}